// round 1
// baseline (speedup 1.0000x reference)
#include <cuda_runtime.h>
#include <cuda_bf16.h>
#include <cstdint>

// Problem constants (fixed shapes from reference)
#define M_DIM 8192      // B*S = 4*2048
#define N_DIM 4096      // OUT
#define K_DIM 4096      // IN
#define NUM_V 1024      // IN/4
#define LUT_SIZE 256

// Scratch (sanctioned __device__ globals)
__device__ float g_X[(size_t)M_DIM * K_DIM];   // tf32-rounded x
__device__ float g_W[(size_t)N_DIM * K_DIM];   // reconstructed tf32-rounded W [N][K]

__device__ __forceinline__ uint32_t f2tf32(float x) {
    uint32_t u;
    asm("cvt.rna.tf32.f32 %0, %1;" : "=r"(u) : "f"(x));
    return u;
}

// ---------------------------------------------------------------------------
// Kernel 1: round x to tf32 (RNA) into g_X
// ---------------------------------------------------------------------------
__global__ void round_x_kernel(const float4* __restrict__ x) {
    size_t i = (size_t)blockIdx.x * blockDim.x + threadIdx.x;  // exactly n4 threads
    float4 v = x[i];
    float4 r;
    r.x = __uint_as_float(f2tf32(v.x));
    r.y = __uint_as_float(f2tf32(v.y));
    r.z = __uint_as_float(f2tf32(v.z));
    r.w = __uint_as_float(f2tf32(v.w));
    reinterpret_cast<float4*>(g_X)[i] = r;
}

// ---------------------------------------------------------------------------
// Kernel 2: reconstruct W[o][k] = scales[o][k/128] * (lut0[v][i0] + lut1[v][i1])
// one thread per (o, v); index reads coalesced in o; LUT gathers hit L1/L2.
// ---------------------------------------------------------------------------
__global__ void reconstruct_kernel(const int* __restrict__ index,
                                   const float* __restrict__ luts,
                                   const float* __restrict__ scales) {
    int v = blockIdx.y;                       // 0..1023
    int o = blockIdx.x * 256 + threadIdx.x;   // 0..4095

    int i0 = index[(size_t)v * N_DIM + o];
    int i1 = index[((size_t)NUM_V + v) * N_DIM + o];
    float s = scales[(size_t)o * (K_DIM / 128) + (v >> 5)];

    const float4* lut0 = reinterpret_cast<const float4*>(luts) + (size_t)v * LUT_SIZE;
    const float4* lut1 = reinterpret_cast<const float4*>(luts) + ((size_t)NUM_V + v) * LUT_SIZE;
    float4 a = lut0[i0];
    float4 b = lut1[i1];

    float4 w;
    w.x = __uint_as_float(f2tf32((a.x + b.x) * s));
    w.y = __uint_as_float(f2tf32((a.y + b.y) * s));
    w.z = __uint_as_float(f2tf32((a.z + b.z) * s));
    w.w = __uint_as_float(f2tf32((a.w + b.w) * s));

    reinterpret_cast<float4*>(g_W)[(size_t)o * NUM_V + v] = w;
}

// ---------------------------------------------------------------------------
// Kernel 3: tf32 GEMM  C[M,N] = A[M,K] * B[N,K]^T + bias
// 128x128x32 CTA tile, double-buffered cp.async, mma.sync m16n8k8 tf32.
// ---------------------------------------------------------------------------
#define TM 128
#define TN 128
#define TK 32
#define RS 36   // padded smem row stride (floats): conflict-free frag loads

__device__ __forceinline__ void cp16(void* s, const void* g) {
    uint32_t sa = (uint32_t)__cvta_generic_to_shared(s);
    asm volatile("cp.async.cg.shared.global [%0], [%1], 16;\n" :: "r"(sa), "l"(g));
}

__device__ __forceinline__ void mma_tf32(float c[4], const uint32_t a[4], const uint32_t b[2]) {
    asm volatile(
        "mma.sync.aligned.m16n8k8.row.col.f32.tf32.tf32.f32 "
        "{%0,%1,%2,%3}, {%4,%5,%6,%7}, {%8,%9}, {%0,%1,%2,%3};\n"
        : "+f"(c[0]), "+f"(c[1]), "+f"(c[2]), "+f"(c[3])
        : "r"(a[0]), "r"(a[1]), "r"(a[2]), "r"(a[3]), "r"(b[0]), "r"(b[1]));
}

__global__ __launch_bounds__(256, 2)
void gemm_tf32_kernel(const float* __restrict__ bias, float* __restrict__ C) {
    extern __shared__ float sm[];
    float* As = sm;                 // [2][TM][RS]
    float* Bs = sm + 2 * TM * RS;   // [2][TN][RS]

    const float* A = g_X;
    const float* B = g_W;

    const int tid  = threadIdx.x;
    const int warp = tid >> 5;
    const int lane = tid & 31;
    const int wm   = warp >> 2;        // 0..1 -> 64 rows of M
    const int wn   = warp & 3;         // 0..3 -> 32 cols of N
    const int grp  = lane >> 2;        // 0..7
    const int tig  = lane & 3;         // 0..3

    const size_t m0 = (size_t)blockIdx.y * TM;
    const size_t n0 = (size_t)blockIdx.x * TN;

    float acc[4][4][4];
    #pragma unroll
    for (int i = 0; i < 4; i++)
        #pragma unroll
        for (int j = 0; j < 4; j++)
            #pragma unroll
            for (int r = 0; r < 4; r++) acc[i][j][r] = 0.0f;

    const int nK = K_DIM / TK;   // 128

    // ---- tile loader ----
    // 1024 float4 per operand tile; 256 threads * 4 each.
    #define LOAD_TILE(buf, kt)                                                      \
        {                                                                           \
            int k0 = (kt) * TK;                                                     \
            _Pragma("unroll")                                                       \
            for (int i = 0; i < 4; i++) {                                           \
                int idx = tid + i * 256;                                            \
                int row = idx >> 3;                                                 \
                int c4  = (idx & 7) << 2;                                           \
                cp16(As + (buf) * TM * RS + row * RS + c4,                          \
                     A + (m0 + row) * K_DIM + k0 + c4);                             \
                cp16(Bs + (buf) * TN * RS + row * RS + c4,                          \
                     B + (n0 + row) * K_DIM + k0 + c4);                             \
            }                                                                       \
            asm volatile("cp.async.commit_group;\n" ::);                            \
        }

    LOAD_TILE(0, 0);

    for (int kt = 0; kt < nK; kt++) {
        if (kt + 1 < nK) {
            LOAD_TILE((kt + 1) & 1, kt + 1);
            asm volatile("cp.async.wait_group 1;\n" ::);
        } else {
            asm volatile("cp.async.wait_group 0;\n" ::);
        }
        __syncthreads();

        const float* Ab = As + (kt & 1) * TM * RS;
        const float* Bb = Bs + (kt & 1) * TN * RS;

        #pragma unroll
        for (int k8 = 0; k8 < 4; k8++) {
            int kb = k8 * 8 + tig;
            uint32_t af[4][4], bf[4][2];
            #pragma unroll
            for (int mi = 0; mi < 4; mi++) {
                const float* p = Ab + (wm * 64 + mi * 16 + grp) * RS + kb;
                af[mi][0] = __float_as_uint(p[0]);
                af[mi][2] = __float_as_uint(p[4]);
                p += 8 * RS;
                af[mi][1] = __float_as_uint(p[0]);
                af[mi][3] = __float_as_uint(p[4]);
            }
            #pragma unroll
            for (int ni = 0; ni < 4; ni++) {
                const float* p = Bb + (wn * 32 + ni * 8 + grp) * RS + kb;
                bf[ni][0] = __float_as_uint(p[0]);
                bf[ni][1] = __float_as_uint(p[4]);
            }
            #pragma unroll
            for (int mi = 0; mi < 4; mi++)
                #pragma unroll
                for (int ni = 0; ni < 4; ni++)
                    mma_tf32(acc[mi][ni], af[mi], bf[ni]);
        }
        __syncthreads();
    }

    // ---- epilogue: + bias, fp32 out ----
    #pragma unroll
    for (int mi = 0; mi < 4; mi++) {
        size_t m = m0 + wm * 64 + mi * 16 + grp;
        #pragma unroll
        for (int ni = 0; ni < 4; ni++) {
            size_t n = n0 + wn * 32 + ni * 8 + tig * 2;
            float b0 = bias[n], b1 = bias[n + 1];
            float2 r0 = make_float2(acc[mi][ni][0] + b0, acc[mi][ni][1] + b1);
            float2 r1 = make_float2(acc[mi][ni][2] + b0, acc[mi][ni][3] + b1);
            *reinterpret_cast<float2*>(C + m * N_DIM + n)       = r0;
            *reinterpret_cast<float2*>(C + (m + 8) * N_DIM + n) = r1;
        }
    }
}

// ---------------------------------------------------------------------------
// Launch
// ---------------------------------------------------------------------------
extern "C" void kernel_launch(void* const* d_in, const int* in_sizes, int n_in,
                              void* d_out, int out_size) {
    const float* x      = (const float*)d_in[0];
    const int*   index  = (const int*)d_in[1];
    const float* luts   = (const float*)d_in[2];
    const float* scales = (const float*)d_in[3];
    const float* bias   = (const float*)d_in[4];
    float* out = (float*)d_out;

    // 1) round x to tf32: 8192*4096/4 = 8,388,608 float4 = 8192 blocks * 1024
    round_x_kernel<<<8192, 1024>>>(reinterpret_cast<const float4*>(x));

    // 2) reconstruct weight
    {
        dim3 grid(N_DIM / 256, NUM_V);
        reconstruct_kernel<<<grid, 256>>>(index, luts, scales);
    }

    // 3) GEMM
    {
        static int smem_set = 0;
        const int smem_bytes = 4 * TM * RS * sizeof(float);  // 2 buf * (A+B) = 73728
        if (!smem_set) {
            cudaFuncSetAttribute(gemm_tf32_kernel,
                                 cudaFuncAttributeMaxDynamicSharedMemorySize, smem_bytes);
            smem_set = 1;
        }
        dim3 grid(N_DIM / TN, M_DIM / TM);  // (32, 64)
        gemm_tf32_kernel<<<grid, 256, smem_bytes>>>(bias, out);
    }
}

// round 3
// speedup vs baseline: 2.3742x; 2.3742x over previous
#include <cuda_runtime.h>
#include <cuda_fp16.h>
#include <cstdint>

// Problem constants (fixed shapes)
#define M_DIM 8192      // B*S
#define N_DIM 4096      // OUT
#define K_DIM 4096      // IN
#define NUM_V 1024      // IN/4
#define LUT_SIZE 256

// Scratch (sanctioned __device__ globals)
__device__ __half g_Xh[(size_t)M_DIM * K_DIM];   // fp16-rounded x      (64 MB)
__device__ __half g_Wh[(size_t)N_DIM * K_DIM];   // reconstructed W[N][K] (32 MB)

// ---------------------------------------------------------------------------
// Kernel 1: round x to fp16
// ---------------------------------------------------------------------------
__global__ void round_x_kernel(const float4* __restrict__ x) {
    size_t i = (size_t)blockIdx.x * blockDim.x + threadIdx.x;
    float4 v = x[i];
    __half2 h0 = __float22half2_rn(make_float2(v.x, v.y));
    __half2 h1 = __float22half2_rn(make_float2(v.z, v.w));
    uint2 o;
    o.x = *reinterpret_cast<uint32_t*>(&h0);
    o.y = *reinterpret_cast<uint32_t*>(&h1);
    reinterpret_cast<uint2*>(g_Xh)[i] = o;
}

// ---------------------------------------------------------------------------
// Kernel 2: reconstruct W[o][k] = scales[o][k/128] * (lut0 + lut1), to fp16
// ---------------------------------------------------------------------------
__global__ void reconstruct_kernel(const int* __restrict__ index,
                                   const float* __restrict__ luts,
                                   const float* __restrict__ scales) {
    int v = blockIdx.y;
    int o = blockIdx.x * 256 + threadIdx.x;

    int i0 = index[(size_t)v * N_DIM + o];
    int i1 = index[((size_t)NUM_V + v) * N_DIM + o];
    float s = scales[(size_t)o * (K_DIM / 128) + (v >> 5)];

    const float4* lut0 = reinterpret_cast<const float4*>(luts) + (size_t)v * LUT_SIZE;
    const float4* lut1 = reinterpret_cast<const float4*>(luts) + ((size_t)NUM_V + v) * LUT_SIZE;
    float4 a = lut0[i0];
    float4 b = lut1[i1];

    __half2 h0 = __float22half2_rn(make_float2((a.x + b.x) * s, (a.y + b.y) * s));
    __half2 h1 = __float22half2_rn(make_float2((a.z + b.z) * s, (a.w + b.w) * s));
    uint2 w;
    w.x = *reinterpret_cast<uint32_t*>(&h0);
    w.y = *reinterpret_cast<uint32_t*>(&h1);
    reinterpret_cast<uint2*>(g_Wh)[(size_t)o * NUM_V + v] = w;
}

// ---------------------------------------------------------------------------
// Kernel 3: fp16 GEMM via mma.sync m16n8k16, ldmatrix feeds, cp.async pipe
// C[M,N] = A[M,K] * B[N,K]^T + bias   (fp32 accumulate, fp32 out)
// CTA tile 128x128, BK=64 halfs (128B rows, XOR-8 swizzle), 3-stage pipeline.
// 8 warps: 2(M) x 4(N), warp tile 64x32.
// ---------------------------------------------------------------------------
#define TM 128
#define TN 128
#define BK 64
#define PIPE 3
#define NSTAGE (K_DIM / BK)              // 64
#define STAGE_A_BYTES (TM * BK * 2)      // 16384
#define STAGE_BYTES (2 * STAGE_A_BYTES)  // 32768 (A then B)
#define SMEM_TOTAL (PIPE * STAGE_BYTES)  // 98304

__device__ __forceinline__ void cp16s(uint32_t sa, const void* g) {
    asm volatile("cp.async.cg.shared.global [%0], [%1], 16;\n" :: "r"(sa), "l"(g));
}

__device__ __forceinline__ void ldsm_x4(uint32_t r[4], uint32_t addr) {
    asm volatile("ldmatrix.sync.aligned.m8n8.x4.shared.b16 {%0,%1,%2,%3}, [%4];"
                 : "=r"(r[0]), "=r"(r[1]), "=r"(r[2]), "=r"(r[3]) : "r"(addr));
}

__device__ __forceinline__ void mma_f16(float c[4], const uint32_t a[4],
                                        uint32_t b0, uint32_t b1) {
    asm volatile(
        "mma.sync.aligned.m16n8k16.row.col.f32.f16.f16.f32 "
        "{%0,%1,%2,%3}, {%4,%5,%6,%7}, {%8,%9}, {%0,%1,%2,%3};\n"
        : "+f"(c[0]), "+f"(c[1]), "+f"(c[2]), "+f"(c[3])
        : "r"(a[0]), "r"(a[1]), "r"(a[2]), "r"(a[3]), "r"(b0), "r"(b1));
}

__global__ __launch_bounds__(256, 2)
void gemm_f16_kernel(const float* __restrict__ bias, float* __restrict__ C) {
    extern __shared__ char smem_raw[];
    const uint32_t smem = (uint32_t)__cvta_generic_to_shared(smem_raw);
    const int tid  = threadIdx.x;
    const int warp = tid >> 5;
    const int lane = tid & 31;
    const int wm   = warp >> 2;   // 0..1 : 64 M rows
    const int wn   = warp & 3;    // 0..3 : 32 N cols

    // --- raster: groups of 512 CTAs = 64 M-tiles x 8 N-tiles ---
    const int bid = blockIdx.x;
    const int gid = bid >> 9;
    const int rr  = bid & 511;
    const size_t m0 = (size_t)(rr >> 3) * TM;
    const size_t n0 = (size_t)((gid << 3) + (rr & 7)) * TN;

    // --- loader geometry: thread -> (row = tid>>3, 16B-col = tid&7) ---
    const int lrow = tid >> 3;          // 0..31
    const int lcg  = tid & 7;           // 0..7
    const uint32_t sdst = (uint32_t)(lrow * 128 + ((lcg ^ (lrow & 7)) * 16));
    const __half* gA0 = g_Xh + (m0 + lrow) * K_DIM + lcg * 8;
    const __half* gB0 = g_Wh + (n0 + lrow) * K_DIM + lcg * 8;

    #define LOAD_STAGE(st, buf)                                                   \
        {                                                                         \
            const __half* ga = gA0 + (st) * BK;                                   \
            const __half* gb = gB0 + (st) * BK;                                   \
            uint32_t sa = smem + (buf) * STAGE_BYTES + sdst;                      \
            uint32_t sb = sa + STAGE_A_BYTES;                                     \
            _Pragma("unroll")                                                     \
            for (int i = 0; i < 4; i++) {                                         \
                cp16s(sa + i * (32 * 128), ga + (size_t)i * 32 * K_DIM);          \
                cp16s(sb + i * (32 * 128), gb + (size_t)i * 32 * K_DIM);          \
            }                                                                     \
            asm volatile("cp.async.commit_group;\n" ::);                          \
        }

    // --- fragment-load geometry (ldmatrix) ---
    // A: lanes 0-15 -> rows 0..15 (k lo 16B), lanes 16-31 -> rows 0..15 (k hi 16B)
    const int aRow  = wm * 64 + (lane & 15);
    const int aKsel = lane >> 4;                 // 0/1
    const uint32_t aBase = (uint32_t)(aRow * 128);
    const int aXor  = aRow & 7;
    // B: mats (n0-7,k lo),(n0-7,k hi),(n8-15,k lo),(n8-15,k hi)
    const int nRow  = wn * 32 + (lane & 7) + ((lane >> 4) << 3);
    const int bKsel = (lane >> 3) & 1;
    const uint32_t bBase = (uint32_t)(STAGE_A_BYTES + nRow * 128);
    const int bXor  = nRow & 7;

    float acc[4][4][4];
    #pragma unroll
    for (int i = 0; i < 4; i++)
        #pragma unroll
        for (int j = 0; j < 4; j++)
            #pragma unroll
            for (int r = 0; r < 4; r++) acc[i][j][r] = 0.0f;

    LOAD_STAGE(0, 0);
    LOAD_STAGE(1, 1);

    for (int kt = 0; kt < NSTAGE; kt++) {
        const int buf = kt % PIPE;
        if (kt + 1 < NSTAGE) {
            asm volatile("cp.async.wait_group 1;\n" ::);
        } else {
            asm volatile("cp.async.wait_group 0;\n" ::);
        }
        __syncthreads();

        const uint32_t sbase = smem + buf * STAGE_BYTES;

        #pragma unroll
        for (int ks = 0; ks < 4; ks++) {
            uint32_t af[4][4];
            #pragma unroll
            for (int mi = 0; mi < 4; mi++) {
                uint32_t addr = sbase + aBase + mi * (16 * 128)
                              + (uint32_t)((((ks * 2 + aKsel) ^ aXor)) * 16);
                ldsm_x4(af[mi], addr);
            }
            uint32_t bf[2][4];
            #pragma unroll
            for (int p = 0; p < 2; p++) {
                uint32_t addr = sbase + bBase + p * (16 * 128)
                              + (uint32_t)((((ks * 2 + bKsel) ^ bXor)) * 16);
                ldsm_x4(bf[p], addr);
            }
            #pragma unroll
            for (int mi = 0; mi < 4; mi++) {
                #pragma unroll
                for (int ni = 0; ni < 4; ni++) {
                    mma_f16(acc[mi][ni], af[mi], bf[ni >> 1][(ni & 1) * 2],
                            bf[ni >> 1][(ni & 1) * 2 + 1]);
                }
            }
        }
        __syncthreads();

        if (kt + 2 < NSTAGE) {
            LOAD_STAGE(kt + 2, (kt + 2) % PIPE);
        }
    }

    // --- epilogue: + bias, fp32 out ---
    const int g  = lane >> 2;
    const int t2 = (lane & 3) * 2;
    #pragma unroll
    for (int mi = 0; mi < 4; mi++) {
        size_t m = m0 + wm * 64 + mi * 16 + g;
        float* c0 = C + m * N_DIM;
        float* c1 = C + (m + 8) * N_DIM;
        #pragma unroll
        for (int ni = 0; ni < 4; ni++) {
            size_t n = n0 + wn * 32 + ni * 8 + t2;
            float b0 = bias[n], b1 = bias[n + 1];
            *reinterpret_cast<float2*>(c0 + n) =
                make_float2(acc[mi][ni][0] + b0, acc[mi][ni][1] + b1);
            *reinterpret_cast<float2*>(c1 + n) =
                make_float2(acc[mi][ni][2] + b0, acc[mi][ni][3] + b1);
        }
    }
    #undef LOAD_STAGE
}

// ---------------------------------------------------------------------------
// Launch
// ---------------------------------------------------------------------------
extern "C" void kernel_launch(void* const* d_in, const int* in_sizes, int n_in,
                              void* d_out, int out_size) {
    const float* x      = (const float*)d_in[0];
    const int*   index  = (const int*)d_in[1];
    const float* luts   = (const float*)d_in[2];
    const float* scales = (const float*)d_in[3];
    const float* bias   = (const float*)d_in[4];
    float* out = (float*)d_out;

    // 1) x -> fp16: 8192*4096/4 = 8,388,608 float4 threads
    round_x_kernel<<<8192, 1024>>>(reinterpret_cast<const float4*>(x));

    // 2) reconstruct weight -> fp16
    {
        dim3 grid(N_DIM / 256, NUM_V);
        reconstruct_kernel<<<grid, 256>>>(index, luts, scales);
    }

    // 3) GEMM
    {
        static int attr_set = 0;
        if (!attr_set) {
            cudaFuncSetAttribute(gemm_f16_kernel,
                                 cudaFuncAttributeMaxDynamicSharedMemorySize, SMEM_TOTAL);
            attr_set = 1;
        }
        dim3 grid((M_DIM / TM) * (N_DIM / TN));  // 2048
        gemm_f16_kernel<<<grid, 256, SMEM_TOTAL>>>(bias, out);
    }
}